// round 4
// baseline (speedup 1.0000x reference)
#include <cuda_runtime.h>
#include <math.h>

#define NT 512
#define DEC_BLOCKS 10

// handoff state (device globals: allocation-free)
__device__ __align__(16) float g_latent[768];
__device__ int g_flag;
__device__ int g_done;

__global__ __launch_bounds__(NT, 1) void fused_kernel(
    const float* __restrict__ t,
    const float* __restrict__ gat_W, const float* __restrict__ a_src, const float* __restrict__ a_dst,
    const float* __restrict__ te_W, const float* __restrict__ te_b, const float* __restrict__ pe,
    const float* __restrict__ qkv_W, const float* __restrict__ qkv_b,
    const float* __restrict__ out_W, const float* __restrict__ out_b,
    const float* __restrict__ ln1_g, const float* __restrict__ ln1_b,
    const float* __restrict__ ff1_W, const float* __restrict__ ff1_b,
    const float* __restrict__ ff2_W, const float* __restrict__ ff2_b,
    const float* __restrict__ ln2_g, const float* __restrict__ ln2_b,
    const float* __restrict__ an_W, const float* __restrict__ an_b,
    const float* __restrict__ pr_W, const float* __restrict__ pr_b,
    float* __restrict__ out)
{
    // ================= DECODER BLOCKS (0..9) =================
    if (blockIdx.x < DEC_BLOCKS) {
        int warp = blockIdx.x * 16 + (threadIdx.x >> 5);   // 0..159
        int lane = threadIdx.x & 31;

        const float* wr;
        float bias;
        bool sig;
        if (warp < 32) { wr = an_W + warp * 768;        bias = an_b[warp];      sig = false; }
        else           { wr = pr_W + (warp - 32) * 768; bias = pr_b[warp - 32]; sig = true;  }

        const float4* w4p = (const float4*)wr;
        float4 w[6];
#pragma unroll
        for (int i = 0; i < 6; i++) w[i] = w4p[i * 32 + lane];

        if (lane == 0) {
            volatile int* fl = &g_flag;
            while (*fl == 0) { __nanosleep(32); }
        }
        __syncwarp();
        __threadfence();

        const float4* lat4 = (const float4*)g_latent;
        float s = 0.f;
#pragma unroll
        for (int i = 0; i < 6; i++) {
            float4 x = __ldcg(&lat4[i * 32 + lane]);
            s += w[i].x*x.x + w[i].y*x.y + w[i].z*x.z + w[i].w*x.w;
        }
#pragma unroll
        for (int o = 16; o; o >>= 1) s += __shfl_down_sync(0xffffffffu, s, o);

        if (lane == 0) {
            s += bias;
            if (sig) s = 1.f / (1.f + __expf(-s));
            out[warp] = s;
        }

        __syncthreads();
        if (threadIdx.x == 0) {
            int d = atomicAdd(&g_done, 1);
            if (d == DEC_BLOCKS - 1) {
                g_done = 0;
                __threadfence();
                *(volatile int*)&g_flag = 0;
            }
        }
        return;
    }

    // ================= ENCODER BLOCK (10) =================
    extern __shared__ float sm[];
    float* s_t    = sm;            // 144
    float* s_gatW = sm + 144;      // 48
    float* s_as   = sm + 192;      // 16
    float* s_ad   = sm + 208;      // 16
    float* s_teW  = sm + 224;      // 320  (16 rows * 20)
    float* s_teb  = sm + 544;      // 16
    float* s_pe   = sm + 560;      // 48
    float* s_qkvW = sm + 608;      // 1920 (2*48 rows * 20)
    float* s_qkvb = sm + 2528;     // 96
    float* s_outW = sm + 2624;     // 640  (2*16 rows * 20)
    float* s_outb = sm + 3264;     // 32
    float* s_ln1g = sm + 3296;     // 32
    float* s_ln1b = sm + 3328;     // 32
    float* s_ff1W = sm + 3360;     // 2560 (2*64 rows * 20)
    float* s_ff1b = sm + 5920;     // 128
    float* s_ff2W = sm + 6048;     // 2176 (2*16 rows * 68)
    float* s_ff2b = sm + 8224;     // 32
    float* s_ln2g = sm + 8256;     // 32
    float* s_ln2b = sm + 8288;     // 32
    // activations: token rows padded to stride 20 (float4-aligned, low conflict)
    float* A_h    = sm + 8320;     // 48*20 = 960
    float* A_al   = sm + 9280;     // 48*20 (alpha rows, [w*16+dst][20])
    float* A_xe   = sm + 10240;    // 960
    float* A_ctx  = sm + 11200;    // 960
    float* A_qkv  = sm + 12160;    // 48*49 = 2352 (odd stride -> conflict-free scalar)
    float* A_hid  = sm + 14512;    // 48*65 = 3120
    float* A_e    = sm + 17632;    // 96

    const int tid  = threadIdx.x;
    const int warp = tid >> 5;
    const int lane = tid & 31;
    const int g    = warp & 1;          // token group (lanes 0-31 / 32-47)
    const int tk   = g * 32 + lane;     // token id
    const int pp   = warp >> 1;         // warp-pair id 0..7
    const bool tok_ok = tk < 48;

    // ---- preload all weights to smem (one time, coalesced) ----
    for (int i = tid; i < 144; i += NT) s_t[i] = t[i];
    for (int i = tid; i < 48; i += NT)  s_gatW[i] = gat_W[i];
    if (tid < 16) { s_as[tid] = a_src[tid]; s_ad[tid] = a_dst[tid]; s_teb[tid] = te_b[tid]; }
    for (int i = tid; i < 256; i += NT)  s_teW[(i >> 4) * 20 + (i & 15)] = te_W[i];
    for (int i = tid; i < 48; i += NT)   s_pe[i] = pe[i];
    for (int i = tid; i < 1536; i += NT) s_qkvW[(i >> 4) * 20 + (i & 15)] = qkv_W[i];
    for (int i = tid; i < 96; i += NT)   s_qkvb[i] = qkv_b[i];
    for (int i = tid; i < 512; i += NT)  s_outW[(i >> 4) * 20 + (i & 15)] = out_W[i];
    if (tid < 32) {
        s_outb[tid] = out_b[tid];
        s_ln1g[tid] = ln1_g[tid]; s_ln1b[tid] = ln1_b[tid];
        s_ln2g[tid] = ln2_g[tid]; s_ln2b[tid] = ln2_b[tid];
        s_ff2b[tid] = ff2_b[tid];
    }
    for (int i = tid; i < 2048; i += NT) s_ff1W[(i >> 4) * 20 + (i & 15)] = ff1_W[i];
    for (int i = tid; i < 128; i += NT)  s_ff1b[i] = ff1_b[i];
    for (int i = tid; i < 2048; i += NT) s_ff2W[(i >> 6) * 68 + (i & 63)] = ff2_W[i];
    __syncthreads();

    // ---- GAT: h[tk][f] = x[tk] @ gat_W   (tiny: 3 FMA each) ----
    for (int idx = tid; idx < 768; idx += NT) {
        int tkx = idx >> 4, f = idx & 15;
        const float* xr = s_t + tkx * 3;
        A_h[tkx * 20 + f] = xr[0]*s_gatW[f] + xr[1]*s_gatW[16+f] + xr[2]*s_gatW[32+f];
    }
    __syncthreads();

    // ---- e_src / e_dst (96 dot16s) ----
    if (tid < 96) {
        int which = tid >= 48, idx = tid - which * 48;
        const float* a = which ? s_ad : s_as;
        const float4* r4 = (const float4*)(A_h + idx * 20);
        const float4* a4 = (const float4*)a;
        float s = 0.f;
#pragma unroll
        for (int i = 0; i < 4; i++) {
            float4 x = r4[i], y = a4[i];
            s += x.x*y.x + x.y*y.y + x.z*y.z + x.w*y.w;
        }
        A_e[tid] = s;
    }
    __syncthreads();

    // ---- alpha = softmax over sources, per (w,dst) ----
    if (tid < 48) {
        int w = tid >> 4;
        float ed = A_e[48 + tid];
        float vals[16], mx = -1e30f;
#pragma unroll
        for (int s = 0; s < 16; s++) {
            float e = A_e[w * 16 + s] + ed;
            e = (e > 0.f) ? e : 0.2f * e;
            vals[s] = e; mx = fmaxf(mx, e);
        }
        float sum = 0.f;
#pragma unroll
        for (int s = 0; s < 16; s++) { vals[s] = __expf(vals[s] - mx); sum += vals[s]; }
        float inv = 1.f / sum;
#pragma unroll
        for (int s = 0; s < 16; s++) A_al[tid * 20 + s] = vals[s] * inv;
    }
    __syncthreads();

    // ---- gat_out[w,dst,f] = elu( sum_s alpha[w,dst,s]*h[w,s,f] ) ----
    // warps 0..11: ww = warp>>2, f-group = warp&3; lane = dst (<16)
    if (warp < 12 && lane < 16) {
        int ww = warp >> 2, fg = warp & 3;
        float al[16];
        const float4* al4 = (const float4*)(A_al + (ww * 16 + lane) * 20);
#pragma unroll
        for (int i = 0; i < 4; i++) {
            float4 v = al4[i];
            al[4*i] = v.x; al[4*i+1] = v.y; al[4*i+2] = v.z; al[4*i+3] = v.w;
        }
#pragma unroll
        for (int i4 = 0; i4 < 4; i4++) {
            int f = fg * 4 + i4;
            float s = 0.f;
            const float* hc = A_h + ww * 320 + f;   // broadcast (warp-uniform addr)
#pragma unroll
            for (int ss = 0; ss < 16; ss++) s += al[ss] * hc[ss * 20];
            A_ctx[(ww * 16 + lane) * 20 + f] = (s > 0.f) ? s : (__expf(s) - 1.f);
        }
    }
    __syncthreads();

    // ---- xe = gat_out @ te_W^T + te_b + pe : lane=token, 2 outputs/lane ----
    if (tok_ok) {
        float x[16];
        const float4* x4 = (const float4*)(A_ctx + tk * 20);
#pragma unroll
        for (int i = 0; i < 4; i++) {
            float4 v = x4[i];
            x[4*i] = v.x; x[4*i+1] = v.y; x[4*i+2] = v.z; x[4*i+3] = v.w;
        }
        int w = tk >> 4;
#pragma unroll
        for (int i2 = 0; i2 < 2; i2++) {
            int d = pp + i2 * 8;
            const float* wd = s_teW + d * 20;      // broadcast
            float s = s_teb[d] + s_pe[w * 16 + d];
#pragma unroll
            for (int i = 0; i < 16; i++) s += x[i] * wd[i];
            A_xe[tk * 20 + d] = s;
        }
    }
    __syncthreads();

    const float inv_sqrt_hd = 0.35355339059327373f;

    for (int l = 0; l < 2; l++) {
        // ---- qkv: lane=token, 6 outputs/lane, weights broadcast ----
        if (tok_ok) {
            float x[16];
            const float4* x4 = (const float4*)(A_xe + tk * 20);
#pragma unroll
            for (int i = 0; i < 4; i++) {
                float4 v = x4[i];
                x[4*i] = v.x; x[4*i+1] = v.y; x[4*i+2] = v.z; x[4*i+3] = v.w;
            }
#pragma unroll
            for (int i6 = 0; i6 < 6; i6++) {
                int j = pp + i6 * 8;
                const float* wj = s_qkvW + l * 960 + j * 20;   // broadcast
                float s = s_qkvb[l * 48 + j];
#pragma unroll
                for (int i = 0; i < 16; i++) s += x[i] * wj[i];
                A_qkv[tk * 49 + j] = s;
            }
        }
        __syncthreads();

        // ---- attention: 96 units (b, head, query-pos) ----
        if (tid < 96) {
            int b = tid / 6, r = tid - b * 6;
            int hh = r / 3, qs = r - hh * 3;
            const float* q = A_qkv + (qs * 16 + b) * 49 + hh * 8;
            float sc[3], mx = -1e30f;
#pragma unroll
            for (int ks = 0; ks < 3; ks++) {
                const float* k = A_qkv + (ks * 16 + b) * 49 + 16 + hh * 8;
                float s = 0.f;
#pragma unroll
                for (int e = 0; e < 8; e++) s += q[e] * k[e];
                s *= inv_sqrt_hd;
                sc[ks] = s; mx = fmaxf(mx, s);
            }
            float sum = 0.f;
#pragma unroll
            for (int ks = 0; ks < 3; ks++) { sc[ks] = __expf(sc[ks] - mx); sum += sc[ks]; }
            float inv = 1.f / sum;
#pragma unroll
            for (int e = 0; e < 8; e++) {
                float c = 0.f;
#pragma unroll
                for (int ks = 0; ks < 3; ks++) c += sc[ks] * A_qkv[(ks * 16 + b) * 49 + 32 + hh * 8 + e];
                A_ctx[(qs * 16 + b) * 20 + hh * 8 + e] = c * inv;
            }
        }
        __syncthreads();

        // ---- out-proj + residual -> A_h ----
        if (tok_ok) {
            float x[16];
            const float4* x4 = (const float4*)(A_ctx + tk * 20);
#pragma unroll
            for (int i = 0; i < 4; i++) {
                float4 v = x4[i];
                x[4*i] = v.x; x[4*i+1] = v.y; x[4*i+2] = v.z; x[4*i+3] = v.w;
            }
#pragma unroll
            for (int i2 = 0; i2 < 2; i2++) {
                int d = pp + i2 * 8;
                const float* wd = s_outW + l * 320 + d * 20;   // broadcast
                float s = s_outb[l * 16 + d] + A_xe[tk * 20 + d];
#pragma unroll
                for (int i = 0; i < 16; i++) s += x[i] * wd[i];
                A_h[tk * 20 + d] = s;
            }
        }
        __syncthreads();

        // ---- LN1 -> A_xe ----
        if (tid < 48) {
            float x[16];
            const float4* r4 = (const float4*)(A_h + tid * 20);
#pragma unroll
            for (int i = 0; i < 4; i++) {
                float4 v = r4[i];
                x[4*i] = v.x; x[4*i+1] = v.y; x[4*i+2] = v.z; x[4*i+3] = v.w;
            }
            float m = 0.f;
#pragma unroll
            for (int e = 0; e < 16; e++) m += x[e];
            m *= 0.0625f;
            float v = 0.f;
#pragma unroll
            for (int e = 0; e < 16; e++) { float d = x[e] - m; v += d * d; }
            float rin = rsqrtf(v * 0.0625f + 1e-5f);
            const float* gg = s_ln1g + l * 16;
            const float* bb = s_ln1b + l * 16;
#pragma unroll
            for (int e = 0; e < 16; e++) A_xe[tid * 20 + e] = (x[e] - m) * rin * gg[e] + bb[e];
        }
        __syncthreads();

        // ---- ff1 (relu): lane=token, 8 outputs/lane ----
        if (tok_ok) {
            float x[16];
            const float4* x4 = (const float4*)(A_xe + tk * 20);
#pragma unroll
            for (int i = 0; i < 4; i++) {
                float4 v = x4[i];
                x[4*i] = v.x; x[4*i+1] = v.y; x[4*i+2] = v.z; x[4*i+3] = v.w;
            }
#pragma unroll
            for (int i8 = 0; i8 < 8; i8++) {
                int f = pp + i8 * 8;
                const float* wf = s_ff1W + l * 1280 + f * 20;   // broadcast
                float s = s_ff1b[l * 64 + f];
#pragma unroll
                for (int i = 0; i < 16; i++) s += x[i] * wf[i];
                A_hid[tk * 65 + f] = fmaxf(s, 0.f);
            }
        }
        __syncthreads();

        // ---- ff2 + residual -> A_h : lane=token, 2 outputs/lane ----
        if (tok_ok) {
            int d0 = pp, d1 = pp + 8;
            const float* hr = A_hid + tk * 65;                  // per-lane, conflict-free
            const float* w0 = s_ff2W + l * 1088 + d0 * 68;      // broadcast
            const float* w1 = s_ff2W + l * 1088 + d1 * 68;      // broadcast
            float a0 = s_ff2b[l * 16 + d0] + A_xe[tk * 20 + d0];
            float a1 = s_ff2b[l * 16 + d1] + A_xe[tk * 20 + d1];
#pragma unroll
            for (int f = 0; f < 64; f++) {
                float hv = hr[f];
                a0 += hv * w0[f];
                a1 += hv * w1[f];
            }
            A_h[tk * 20 + d0] = a0;
            A_h[tk * 20 + d1] = a1;
        }
        __syncthreads();

        // ---- LN2 -> A_xe ----
        if (tid < 48) {
            float x[16];
            const float4* r4 = (const float4*)(A_h + tid * 20);
#pragma unroll
            for (int i = 0; i < 4; i++) {
                float4 v = r4[i];
                x[4*i] = v.x; x[4*i+1] = v.y; x[4*i+2] = v.z; x[4*i+3] = v.w;
            }
            float m = 0.f;
#pragma unroll
            for (int e = 0; e < 16; e++) m += x[e];
            m *= 0.0625f;
            float v = 0.f;
#pragma unroll
            for (int e = 0; e < 16; e++) { float d = x[e] - m; v += d * d; }
            float rin = rsqrtf(v * 0.0625f + 1e-5f);
            const float* gg = s_ln2g + l * 16;
            const float* bb = s_ln2b + l * 16;
#pragma unroll
            for (int e = 0; e < 16; e++) A_xe[tid * 20 + e] = (x[e] - m) * rin * gg[e] + bb[e];
        }
        __syncthreads();
    }

    // ---- latent (host-major) to global, release flag ----
    for (int idx = tid; idx < 768; idx += NT) {
        int w = idx >> 8, rem = idx & 255, n = rem >> 4, d = rem & 15;
        g_latent[n * 48 + w * 16 + d] = A_xe[(w * 16 + n) * 20 + d];
    }
    __threadfence();
    __syncthreads();
    if (tid == 0) *(volatile int*)&g_flag = 1;
}

extern "C" void kernel_launch(void* const* d_in, const int* in_sizes, int n_in,
                              void* d_out, int out_size) {
    const int smem_bytes = 17728 * 4;
    cudaFuncSetAttribute(fused_kernel, cudaFuncAttributeMaxDynamicSharedMemorySize, smem_bytes);
    fused_kernel<<<DEC_BLOCKS + 1, NT, smem_bytes>>>(
        (const float*)d_in[0],
        (const float*)d_in[2], (const float*)d_in[3], (const float*)d_in[4],
        (const float*)d_in[5], (const float*)d_in[6], (const float*)d_in[7],
        (const float*)d_in[8], (const float*)d_in[9],
        (const float*)d_in[10], (const float*)d_in[11],
        (const float*)d_in[12], (const float*)d_in[13],
        (const float*)d_in[14], (const float*)d_in[15],
        (const float*)d_in[16], (const float*)d_in[17],
        (const float*)d_in[18], (const float*)d_in[19],
        (const float*)d_in[20], (const float*)d_in[21],
        (const float*)d_in[22], (const float*)d_in[23],
        (float*)d_out);
}

// round 5
// speedup vs baseline: 1.1385x; 1.1385x over previous
#include <cuda_runtime.h>
#include <math.h>

#define NT 512
typedef unsigned long long ull;

// ---- packed f32x2 helpers (sm_103a) ----
__device__ __forceinline__ ull pk2(float lo, float hi) {
    ull r; asm("mov.b64 %0, {%1,%2};" : "=l"(r) : "f"(lo), "f"(hi)); return r;
}
__device__ __forceinline__ float2 upk2(ull v) {
    float2 r; asm("mov.b64 {%0,%1}, %2;" : "=f"(r.x), "=f"(r.y) : "l"(v)); return r;
}
__device__ __forceinline__ ull ffma2(ull a, ull b, ull c) {
    ull d; asm("fma.rn.f32x2 %0, %1, %2, %3;" : "=l"(d) : "l"(a), "l"(b), "l"(c)); return d;
}
// load 16 contiguous floats (16B-aligned) into 8 packed pairs
__device__ __forceinline__ void loadx(const float* p, ull* xp) {
    const float4* p4 = (const float4*)p;
#pragma unroll
    for (int i = 0; i < 4; i++) {
        float4 v = p4[i];
        xp[2*i]   = pk2(v.x, v.y);
        xp[2*i+1] = pk2(v.z, v.w);
    }
}
// dot16 with packed x and float4 weight row
__device__ __forceinline__ float dot16p(const ull* xp, const float4* w4) {
    ull a0 = 0ull, a1 = 0ull;
#pragma unroll
    for (int i = 0; i < 4; i++) {
        float4 w = w4[i];
        a0 = ffma2(xp[2*i],   pk2(w.x, w.y), a0);
        a1 = ffma2(xp[2*i+1], pk2(w.z, w.w), a1);
    }
    float2 s0 = upk2(a0), s1 = upk2(a1);
    return (s0.x + s1.x) + (s0.y + s1.y);
}

__global__ __launch_bounds__(NT, 1) void fused_kernel(
    const float* __restrict__ t,
    const float* __restrict__ gat_W, const float* __restrict__ a_src, const float* __restrict__ a_dst,
    const float* __restrict__ te_W, const float* __restrict__ te_b, const float* __restrict__ pe,
    const float* __restrict__ qkv_W, const float* __restrict__ qkv_b,
    const float* __restrict__ out_W, const float* __restrict__ out_b,
    const float* __restrict__ ln1_g, const float* __restrict__ ln1_b,
    const float* __restrict__ ff1_W, const float* __restrict__ ff1_b,
    const float* __restrict__ ff2_W, const float* __restrict__ ff2_b,
    const float* __restrict__ ln2_g, const float* __restrict__ ln2_b,
    const float* __restrict__ an_W, const float* __restrict__ an_b,
    const float* __restrict__ pr_W, const float* __restrict__ pr_b,
    float* __restrict__ out)
{
    const int tid  = threadIdx.x;
    const int warp = tid >> 5;
    const int lane = tid & 31;
    const int g    = warp & 1;
    const int tk   = g * 32 + lane;     // token id for tok_ok mapping
    const int pp   = warp >> 1;         // warp-pair 0..7
    const bool tok_ok = tk < 48;

    // ---- decoder weight prefetch (registers; latency hidden behind encoder) ----
    const int row = blockIdx.x * 16 + warp;   // 0..159
    const float4* wp = (row < 32) ? (const float4*)(an_W + row * 768)
                                  : (const float4*)(pr_W + (row - 32) * 768);
    float bias_reg = (row < 32) ? an_b[row] : pr_b[row - 32];
    float4 wreg[6];
#pragma unroll
    for (int i = 0; i < 6; i++) wreg[i] = wp[i * 32 + lane];

    extern __shared__ float sm[];
    float* s_t    = sm;            // 144
    float* s_gatW = sm + 144;      // 48
    float* s_as   = sm + 192;      // 16
    float* s_ad   = sm + 208;      // 16
    float* s_teW  = sm + 224;      // 320  (16 rows * 20)
    float* s_teb  = sm + 544;      // 16
    float* s_pe   = sm + 560;      // 48
    float* s_qkvW = sm + 608;      // 1920 (2*48 rows * 20)
    float* s_qkvb = sm + 2528;     // 96
    float* s_outW = sm + 2624;     // 640  (2*16 rows * 20)
    float* s_outb = sm + 3264;     // 32
    float* s_ln1g = sm + 3296;     // 32
    float* s_ln1b = sm + 3328;     // 32
    float* s_ff1W = sm + 3360;     // 2560 (2*64 rows * 20)
    float* s_ff1b = sm + 5920;     // 128
    float* s_ff2W = sm + 6048;     // 2176 (2*16 rows * 68)
    float* s_ff2b = sm + 8224;     // 32
    float* s_ln2g = sm + 8256;     // 32
    float* s_ln2b = sm + 8288;     // 32
    float* A_h    = sm + 8320;     // 48*20
    float* A_al   = sm + 9280;     // 48*20
    float* A_xe   = sm + 10240;    // 48*20
    float* A_ctx  = sm + 11200;    // 48*20
    float* A_qkv  = sm + 12160;    // 48*52
    float* A_hid  = sm + 14656;    // 48*68
    float* A_e    = sm + 17920;    // 96

    // ---- preload weights to smem ----
    for (int i = tid; i < 144; i += NT) s_t[i] = t[i];
    for (int i = tid; i < 48; i += NT)  s_gatW[i] = gat_W[i];
    if (tid < 16) { s_as[tid] = a_src[tid]; s_ad[tid] = a_dst[tid]; s_teb[tid] = te_b[tid]; }
    for (int i = tid; i < 256; i += NT)  s_teW[(i >> 4) * 20 + (i & 15)] = te_W[i];
    for (int i = tid; i < 48; i += NT)   s_pe[i] = pe[i];
    for (int i = tid; i < 1536; i += NT) s_qkvW[(i >> 4) * 20 + (i & 15)] = qkv_W[i];
    for (int i = tid; i < 96; i += NT)   s_qkvb[i] = qkv_b[i];
    for (int i = tid; i < 512; i += NT)  s_outW[(i >> 4) * 20 + (i & 15)] = out_W[i];
    if (tid < 32) {
        s_outb[tid] = out_b[tid];
        s_ln1g[tid] = ln1_g[tid]; s_ln1b[tid] = ln1_b[tid];
        s_ln2g[tid] = ln2_g[tid]; s_ln2b[tid] = ln2_b[tid];
        s_ff2b[tid] = ff2_b[tid];
    }
    for (int i = tid; i < 2048; i += NT) s_ff1W[(i >> 4) * 20 + (i & 15)] = ff1_W[i];
    for (int i = tid; i < 128; i += NT)  s_ff1b[i] = ff1_b[i];
    for (int i = tid; i < 2048; i += NT) s_ff2W[(i >> 6) * 68 + (i & 63)] = ff2_W[i];
    __syncthreads();

    // ---- GAT: h = x @ gat_W ----
    for (int idx = tid; idx < 768; idx += NT) {
        int tkx = idx >> 4, f = idx & 15;
        const float* xr = s_t + tkx * 3;
        A_h[tkx * 20 + f] = xr[0]*s_gatW[f] + xr[1]*s_gatW[16+f] + xr[2]*s_gatW[32+f];
    }
    __syncthreads();

    // ---- e_src / e_dst ----
    if (tid < 96) {
        int which = tid >= 48, idx = tid - which * 48;
        ull xp[8]; loadx(A_h + idx * 20, xp);
        A_e[tid] = dot16p(xp, (const float4*)(which ? s_ad : s_as));
    }
    __syncthreads();

    // ---- alpha = softmax over sources per (w,dst) ----
    if (tid < 48) {
        int w = tid >> 4;
        float ed = A_e[48 + tid];
        float vals[16], mx = -1e30f;
#pragma unroll
        for (int s = 0; s < 16; s++) {
            float e = A_e[w * 16 + s] + ed;
            e = (e > 0.f) ? e : 0.2f * e;
            vals[s] = e; mx = fmaxf(mx, e);
        }
        float sum = 0.f;
#pragma unroll
        for (int s = 0; s < 16; s++) { vals[s] = __expf(vals[s] - mx); sum += vals[s]; }
        float inv = 1.f / sum;
#pragma unroll
        for (int s = 0; s < 16; s++) A_al[tid * 20 + s] = vals[s] * inv;
    }
    __syncthreads();

    // ---- gat_out = elu( sum_s alpha * h ) -> A_ctx ----
    if (warp < 12 && lane < 16) {
        int ww = warp >> 2, fg = warp & 3;
        float al[16];
        const float4* al4 = (const float4*)(A_al + (ww * 16 + lane) * 20);
#pragma unroll
        for (int i = 0; i < 4; i++) {
            float4 v = al4[i];
            al[4*i] = v.x; al[4*i+1] = v.y; al[4*i+2] = v.z; al[4*i+3] = v.w;
        }
        ull a0 = 0ull, a1 = 0ull;
#pragma unroll
        for (int ss = 0; ss < 16; ss++) {
            float4 hv = *(const float4*)(A_h + ww * 320 + ss * 20 + fg * 4);  // broadcast
            ull av = pk2(al[ss], al[ss]);
            a0 = ffma2(av, pk2(hv.x, hv.y), a0);
            a1 = ffma2(av, pk2(hv.z, hv.w), a1);
        }
        float2 s0 = upk2(a0), s1 = upk2(a1);
        float r[4] = { s0.x, s0.y, s1.x, s1.y };
#pragma unroll
        for (int i4 = 0; i4 < 4; i4++) {
            float s = r[i4];
            A_ctx[(ww * 16 + lane) * 20 + fg * 4 + i4] = (s > 0.f) ? s : (__expf(s) - 1.f);
        }
    }
    __syncthreads();

    // ---- xe = gat_out @ te_W^T + te_b + pe ----
    if (tok_ok) {
        ull xp[8]; loadx(A_ctx + tk * 20, xp);
        int w = tk >> 4;
#pragma unroll
        for (int i2 = 0; i2 < 2; i2++) {
            int d = pp + i2 * 8;
            A_xe[tk * 20 + d] = s_teb[d] + s_pe[w * 16 + d] +
                                dot16p(xp, (const float4*)(s_teW + d * 20));
        }
    }
    __syncthreads();

    const float inv_sqrt_hd = 0.35355339059327373f;

    for (int l = 0; l < 2; l++) {
        // ---- qkv ----
        if (tok_ok) {
            ull xp[8]; loadx(A_xe + tk * 20, xp);
#pragma unroll
            for (int i6 = 0; i6 < 6; i6++) {
                int j = pp + i6 * 8;
                A_qkv[tk * 52 + j] = s_qkvb[l * 48 + j] +
                    dot16p(xp, (const float4*)(s_qkvW + l * 960 + j * 20));
            }
        }
        __syncthreads();

        // ---- attention ----
        if (tid < 96) {
            int b = tid / 6, r = tid - b * 6;
            int hh = r / 3, qs = r - hh * 3;
            const float* q = A_qkv + (qs * 16 + b) * 52 + hh * 8;
            float sc[3], mx = -1e30f;
#pragma unroll
            for (int ks = 0; ks < 3; ks++) {
                const float* k = A_qkv + (ks * 16 + b) * 52 + 16 + hh * 8;
                float s = 0.f;
#pragma unroll
                for (int e = 0; e < 8; e++) s += q[e] * k[e];
                s *= inv_sqrt_hd;
                sc[ks] = s; mx = fmaxf(mx, s);
            }
            float sum = 0.f;
#pragma unroll
            for (int ks = 0; ks < 3; ks++) { sc[ks] = __expf(sc[ks] - mx); sum += sc[ks]; }
            float inv = 1.f / sum;
#pragma unroll
            for (int e = 0; e < 8; e++) {
                float c = 0.f;
#pragma unroll
                for (int ks = 0; ks < 3; ks++) c += sc[ks] * A_qkv[(ks * 16 + b) * 52 + 32 + hh * 8 + e];
                A_ctx[(qs * 16 + b) * 20 + hh * 8 + e] = c * inv;
            }
        }
        __syncthreads();

        // ---- out-proj + residual + LN1 (fused; 2 threads per token) ----
        if (tid < 96) {
            int tk2 = tid >> 1, h2 = tid & 1;
            ull xp[8]; loadx(A_ctx + tk2 * 20, xp);
            float4 r0 = *(const float4*)(A_xe + tk2 * 20 + h2 * 8);
            float4 r1 = *(const float4*)(A_xe + tk2 * 20 + h2 * 8 + 4);
            float resid[8] = { r0.x, r0.y, r0.z, r0.w, r1.x, r1.y, r1.z, r1.w };
            float y[8];
#pragma unroll
            for (int k = 0; k < 8; k++) {
                int d = h2 * 8 + k;
                y[k] = s_outb[l * 16 + d] + resid[k] +
                       dot16p(xp, (const float4*)(s_outW + l * 320 + d * 20));
            }
            float ls = 0.f, lq = 0.f;
#pragma unroll
            for (int k = 0; k < 8; k++) { ls += y[k]; lq += y[k] * y[k]; }
            ls += __shfl_xor_sync(0xffffffffu, ls, 1);
            lq += __shfl_xor_sync(0xffffffffu, lq, 1);
            float m = ls * 0.0625f;
            float rin = rsqrtf(lq * 0.0625f - m * m + 1e-5f);
#pragma unroll
            for (int k = 0; k < 8; k++) {
                int d = h2 * 8 + k;
                y[k] = (y[k] - m) * rin * s_ln1g[l * 16 + d] + s_ln1b[l * 16 + d];
            }
            *(float4*)(A_xe + tk2 * 20 + h2 * 8)     = make_float4(y[0], y[1], y[2], y[3]);
            *(float4*)(A_xe + tk2 * 20 + h2 * 8 + 4) = make_float4(y[4], y[5], y[6], y[7]);
        }
        __syncthreads();

        // ---- ff1 (relu), 8 contiguous outputs per lane ----
        if (tok_ok) {
            ull xp[8]; loadx(A_xe + tk * 20, xp);
            float y[8];
#pragma unroll
            for (int k = 0; k < 8; k++) {
                int f = pp * 8 + k;
                y[k] = fmaxf(s_ff1b[l * 64 + f] +
                             dot16p(xp, (const float4*)(s_ff1W + l * 1280 + f * 20)), 0.f);
            }
            *(float4*)(A_hid + tk * 68 + pp * 8)     = make_float4(y[0], y[1], y[2], y[3]);
            *(float4*)(A_hid + tk * 68 + pp * 8 + 4) = make_float4(y[4], y[5], y[6], y[7]);
        }
        __syncthreads();

        // ---- ff2 + residual + LN2 (fused; 4 threads per token) ----
        if (tid < 192) {
            int tk2 = tid >> 2, q = tid & 3;
            const float4* hr = (const float4*)(A_hid + tk2 * 68);
            const float4* w40 = (const float4*)(s_ff2W + l * 1088 + (q * 4 + 0) * 68);
            const float4* w41 = (const float4*)(s_ff2W + l * 1088 + (q * 4 + 1) * 68);
            const float4* w42 = (const float4*)(s_ff2W + l * 1088 + (q * 4 + 2) * 68);
            const float4* w43 = (const float4*)(s_ff2W + l * 1088 + (q * 4 + 3) * 68);
            ull a0[4] = {0,0,0,0}, a1[4] = {0,0,0,0};
#pragma unroll
            for (int i = 0; i < 16; i++) {
                float4 h4 = hr[i];
                ull h0 = pk2(h4.x, h4.y), h1 = pk2(h4.z, h4.w);
                float4 w0 = w40[i], w1 = w41[i], w2 = w42[i], w3 = w43[i];
                a0[0] = ffma2(h0, pk2(w0.x, w0.y), a0[0]); a1[0] = ffma2(h1, pk2(w0.z, w0.w), a1[0]);
                a0[1] = ffma2(h0, pk2(w1.x, w1.y), a0[1]); a1[1] = ffma2(h1, pk2(w1.z, w1.w), a1[1]);
                a0[2] = ffma2(h0, pk2(w2.x, w2.y), a0[2]); a1[2] = ffma2(h1, pk2(w2.z, w2.w), a1[2]);
                a0[3] = ffma2(h0, pk2(w3.x, w3.y), a0[3]); a1[3] = ffma2(h1, pk2(w3.z, w3.w), a1[3]);
            }
            float y[4], ls = 0.f, lq = 0.f;
#pragma unroll
            for (int k = 0; k < 4; k++) {
                int d = q * 4 + k;
                float2 s0 = upk2(a0[k]), s1 = upk2(a1[k]);
                y[k] = (s0.x + s1.x) + (s0.y + s1.y) + s_ff2b[l * 16 + d] + A_xe[tk2 * 20 + d];
                ls += y[k]; lq += y[k] * y[k];
            }
            ls += __shfl_xor_sync(0xffffffffu, ls, 1);
            lq += __shfl_xor_sync(0xffffffffu, lq, 1);
            ls += __shfl_xor_sync(0xffffffffu, ls, 2);
            lq += __shfl_xor_sync(0xffffffffu, lq, 2);
            float m = ls * 0.0625f;
            float rin = rsqrtf(lq * 0.0625f - m * m + 1e-5f);
#pragma unroll
            for (int k = 0; k < 4; k++) {
                int d = q * 4 + k;
                y[k] = (y[k] - m) * rin * s_ln2g[l * 16 + d] + s_ln2b[l * 16 + d];
            }
            *(float4*)(A_xe + tk2 * 20 + q * 4) = make_float4(y[0], y[1], y[2], y[3]);
        }
        __syncthreads();
    }

    // ---- decoder: warp = output row, latent read straight from smem ----
    {
        ull a0 = 0ull, a1 = 0ull;
#pragma unroll
        for (int i = 0; i < 6; i++) {
            int j = i * 128 + 4 * lane;        // latent index (host-major)
            int n = j / 48, rem = j - n * 48;
            int ww = rem >> 4, d = rem & 15;
            float4 x = *(const float4*)(A_xe + (ww * 16 + n) * 20 + d);
            a0 = ffma2(pk2(x.x, x.y), pk2(wreg[i].x, wreg[i].y), a0);
            a1 = ffma2(pk2(x.z, x.w), pk2(wreg[i].z, wreg[i].w), a1);
        }
        float2 s0 = upk2(a0), s1 = upk2(a1);
        float s = (s0.x + s1.x) + (s0.y + s1.y);
#pragma unroll
        for (int o = 16; o; o >>= 1) s += __shfl_xor_sync(0xffffffffu, s, o);
        if (lane == 0) {
            s += bias_reg;
            if (row >= 32) s = 1.f / (1.f + __expf(-s));
            out[row] = s;
        }
    }
}

extern "C" void kernel_launch(void* const* d_in, const int* in_sizes, int n_in,
                              void* d_out, int out_size) {
    const int smem_bytes = 18016 * 4;
    cudaFuncSetAttribute(fused_kernel, cudaFuncAttributeMaxDynamicSharedMemorySize, smem_bytes);
    fused_kernel<<<10, NT, smem_bytes>>>(
        (const float*)d_in[0],
        (const float*)d_in[2], (const float*)d_in[3], (const float*)d_in[4],
        (const float*)d_in[5], (const float*)d_in[6], (const float*)d_in[7],
        (const float*)d_in[8], (const float*)d_in[9],
        (const float*)d_in[10], (const float*)d_in[11],
        (const float*)d_in[12], (const float*)d_in[13],
        (const float*)d_in[14], (const float*)d_in[15],
        (const float*)d_in[16], (const float*)d_in[17],
        (const float*)d_in[18], (const float*)d_in[19],
        (const float*)d_in[20], (const float*)d_in[21],
        (const float*)d_in[22], (const float*)d_in[23],
        (float*)d_out);
}